// round 12
// baseline (speedup 1.0000x reference)
#include <cuda_runtime.h>
#include <cstdint>

// Problem constants
#define B_  32
#define C_  128
#define H_  36
#define W_  100
#define KW  9

// Scratch ping-pong buffers (device globals: no runtime allocation allowed)
__device__ float g_buf0[(size_t)B_ * C_ * H_ * W_];
__device__ float g_buf1[(size_t)B_ * C_ * H_ * W_];

static __device__ __forceinline__ void cluster_sync() {
    asm volatile("barrier.cluster.arrive.aligned;" ::: "memory");
    asm volatile("barrier.cluster.wait.aligned;" ::: "memory");
}

// Per-16-ci-block skew (in floats). Quad permutation makes every
// quarter-warp's 8 lanes hit distinct 16B bank quads for both the vertical
// (4 ciq x 2 consecutive w-tiles) and horizontal (8 ciq) lane mappings.
// NOTE: SKF is NON-monotonic in u, so every block gets a 32-float stride pad
// (see *BLK below) — without it adjacent blocks' regions overlap (R10 bug).
static __device__ __host__ __forceinline__ int SKF(int u) {
    return ((u & 1) << 3) + (((u >> 1) & 1) << 2) + ((u >> 2) << 4);
}

#define FMA2(d, a, b, c) \
    asm("fma.rn.f32x2 %0, %1, %2, %3;" : "=l"(d) : "l"(a), "l"(b), "l"(c))
#define PACK2(d, v) \
    asm("mov.b64 %0, {%1, %1};" : "=l"(d) : "f"(v))
#define UNPACK2(lo, hi, p) \
    asm("mov.b64 {%0, %1}, %2;" : "=f"(lo), "=f"(hi) : "l"(p))

// One SCNN message-passing pass over a [B, C, S, L] tensor:
// scan over dim 2 (length S), 1D conv (K=9, pad 4) along contiguous dim 3.
// Cluster of 4 CTAs per batch; CTA g owns output channels [32g, 32g+32).
// Weights live in SMEM all pass. Each thread: 4 co (2 f32x2 pairs) x 8 w.
// ci loop runs in 16-blocks with skewed+padded smem addressing,
// pipelined p loads, pre-barrier x prefetch, post-barrier own-slice STS.
template <int S, int L, int CI_SPLIT, int BLOCK>
__global__ void __launch_bounds__(BLOCK, 1) __cluster_dims__(4, 1, 1)
scnn_pass(const float* __restrict__ in, const float* __restrict__ wts,
          float* __restrict__ out, int rev)
{
    constexpr int PS   = L + 16;         // padded row stride (4 left, 12 right)
    constexpr int L4   = L / 4;
    constexpr int NWT  = (L + 7) / 8;    // 8-wide w tiles (last may be partial)
    constexpr int CHS  = S * L;
    constexpr int CIN  = C_ / CI_SPLIT;
    constexpr int NBLK = CIN / 16;       // 16-ci blocks per thread
    constexpr int WROW = KW * 32;        // floats per ci in weight smem
    constexpr int WBLK = 16 * WROW + 32; // weight block stride (pad > max SKF)
    constexpr int PBLK = 16 * PS + 32;   // p-row block stride
    constexpr int WFL  = 8 * WBLK + 32;
    constexpr int PPF  = 8 * PBLK + 32;
    constexpr int NX   = (32 * L4 + BLOCK - 1) / BLOCK;   // xsm staging iters

    extern __shared__ float smem[];
    float* wsm = smem;            // [blk pad+skew][ci16][k][co32]
    float* pp  = smem + WFL;      // [blk pad+skew][c16][PS]
    float* xsm = pp + PPF;        // [32 co][L] staged skip-connection row

    const int tid = threadIdx.x;
    const int g   = blockIdx.x;
    const int b   = blockIdx.y;
    const int co0 = g * 32;

    const float* inB  = in  + (size_t)b * C_ * CHS;
    float*       outB = out + (size_t)b * C_ * CHS;

    uint32_t sbase;
    asm("{ .reg .u64 t; cvta.to.shared.u64 t, %1; cvt.u32.u64 %0, t; }"
        : "=r"(sbase) : "l"(smem));

    // address helpers (block-padded + skewed)
    #define PP_OFF(c)  (((c) >> 4) * PBLK + ((c) & 15) * PS + SKF((c) >> 4))
    #define W_OFF(ci)  (((ci) >> 4) * WBLK + ((ci) & 15) * WROW + SKF((ci) >> 4))

    // ---- load weight slice w[co0..co0+31][ci][k] into skewed smem ----
    {
        const float* wg = wts + (size_t)co0 * (C_ * KW);
        for (int idx = tid; idx < 32 * C_ * KW; idx += BLOCK) {
            int col = idx / (C_ * KW);
            int r   = idx - col * (C_ * KW);      // ci*9 + k
            int ci  = r / KW;
            int k   = r - ci * KW;
            wsm[W_OFF(ci) + k * 32 + col] = wg[idx];
        }
    }
    for (int idx = tid; idx < PPF; idx += BLOCK) pp[idx] = 0.0f;

    // ---- thread -> (2 co-pairs = 4 co) x (8 consecutive w), ci split ----
    const int  task = tid / CI_SPLIT;
    const int  ciq  = tid % CI_SPLIT;
    const int  wt   = task % NWT;
    const int  cot  = task / NWT;        // always 0..7 (exact task count)
    const int  w0   = wt * 8;
    const int  colB = cot * 4;
    const int  ci0  = ciq * CIN;
    const bool wb   = (ciq == 0);        // writer thread for this tile
    const bool st2  = (w0 + 4 < L);      // second float4 in range?

    __syncthreads();

    for (int step = 0; step < S; ++step) {
        const int    p      = rev ? (S - 1 - step) : step;
        const size_t rowOff = (size_t)p * L;
        const int    pn     = rev ? (p - 1) : (p + 1);   // next step's row

        if (step == 0) {
            for (int idx = tid; idx < 32 * L4; idx += BLOCK) {
                int c = idx / L4, j = idx - c * L4;
                const size_t o = (size_t)(co0 + c) * CHS + rowOff + 4 * j;
                *reinterpret_cast<float4*>(outB + o) =
                    *reinterpret_cast<const float4*>(inB + o);
            }
            for (int idx = tid; idx < C_ * L4; idx += BLOCK) {
                int c = idx / L4, j = idx - c * L4;
                const float4 v = *reinterpret_cast<const float4*>(
                    inB + (size_t)c * CHS + rowOff + 4 * j);
                *reinterpret_cast<float4*>(&pp[PP_OFF(c) + 4 + 4 * j]) = v;
            }
            #pragma unroll
            for (int it = 0; it < NX; ++it) {
                int idx = tid + it * BLOCK;
                if (idx < 32 * L4) {
                    int c = idx / L4, j = idx - c * L4;
                    *reinterpret_cast<float4*>(&xsm[c * L + 4 * j]) =
                        *reinterpret_cast<const float4*>(
                            inB + (size_t)(co0 + c) * CHS + (size_t)pn * L + 4 * j);
                }
            }
            __syncthreads();
        } else {
            // acc2[pair][j]: pair 0 = co (colB,colB+1), pair 1 = (colB+2,colB+3)
            unsigned long long acc2[2][8];
            #pragma unroll
            for (int pr = 0; pr < 2; ++pr)
                #pragma unroll
                for (int j = 0; j < 8; ++j) acc2[pr][j] = 0ull;

            #pragma unroll
            for (int blk = 0; blk < NBLK; ++blk) {
                const int cib = ci0 + 16 * blk;      // multiple of 16
                const int ub  = cib >> 4;
                const float* prow = pp + ub * PBLK + SKF(ub) + w0;
                uint32_t     wadr = sbase +
                    (uint32_t)(ub * WBLK + SKF(ub) + colB) * 4u;

                // prime the p pipeline for this block
                float4 va = *reinterpret_cast<const float4*>(prow);
                float4 vb = *reinterpret_cast<const float4*>(prow + 4);
                float4 vc = *reinterpret_cast<const float4*>(prow + 8);
                float4 vd = *reinterpret_cast<const float4*>(prow + 12);

                #pragma unroll 2
                for (int i = 0; i < 16; ++i) {
                    unsigned long long vp[16];
                    PACK2(vp[0],  va.x); PACK2(vp[1],  va.y);
                    PACK2(vp[2],  va.z); PACK2(vp[3],  va.w);
                    PACK2(vp[4],  vb.x); PACK2(vp[5],  vb.y);
                    PACK2(vp[6],  vb.z); PACK2(vp[7],  vb.w);
                    PACK2(vp[8],  vc.x); PACK2(vp[9],  vc.y);
                    PACK2(vp[10], vc.z); PACK2(vp[11], vc.w);
                    PACK2(vp[12], vd.x); PACK2(vp[13], vd.y);
                    PACK2(vp[14], vd.z); PACK2(vp[15], vd.w);

                    // prefetch next i's p row during the FMA block
                    prow += PS;
                    if (i < 15) {
                        va = *reinterpret_cast<const float4*>(prow);
                        vb = *reinterpret_cast<const float4*>(prow + 4);
                        vc = *reinterpret_cast<const float4*>(prow + 8);
                        vd = *reinterpret_cast<const float4*>(prow + 12);
                    }

                    #pragma unroll
                    for (int k = 0; k < KW; ++k) {
                        unsigned long long w01, w23;
                        asm("ld.shared.v2.b64 {%0, %1}, [%2];"
                            : "=l"(w01), "=l"(w23)
                            : "r"(wadr + (uint32_t)(k * 128)));
                        #pragma unroll
                        for (int j = 0; j < 8; ++j) {
                            FMA2(acc2[0][j], w01, vp[j + k], acc2[0][j]);
                            FMA2(acc2[1][j], w23, vp[j + k], acc2[1][j]);
                        }
                    }
                    wadr += WROW * 4;
                }
            }

            // unpack packed accumulators -> accf[a = co offset][j]
            float accf[4][8];
            #pragma unroll
            for (int pr = 0; pr < 2; ++pr)
                #pragma unroll
                for (int j = 0; j < 8; ++j)
                    UNPACK2(accf[2 * pr][j], accf[2 * pr + 1][j], acc2[pr][j]);

            if (CI_SPLIT > 1) {                      // reduce across ciq lanes
                #pragma unroll
                for (int a = 0; a < 4; ++a)
                    #pragma unroll
                    for (int j = 0; j < 8; ++j) {
                        float s = accf[a][j];
                        #pragma unroll
                        for (int off = CI_SPLIT >> 1; off > 0; off >>= 1)
                            s += __shfl_down_sync(0xffffffffu, s, off);
                        accf[a][j] = s;
                    }
            }

            // finalize own rows; store to gmem, keep for post-barrier STS
            float4 rr0[4], rr1[4];
            if (wb) {
                #pragma unroll
                for (int a = 0; a < 4; ++a) {
                    const float* xr = &xsm[(colB + a) * L + w0];
                    const size_t o  = (size_t)(co0 + colB + a) * CHS + rowOff + w0;
                    const float4 x0 = *reinterpret_cast<const float4*>(xr);
                    rr0[a].x = x0.x + fmaxf(accf[a][0], 0.0f);
                    rr0[a].y = x0.y + fmaxf(accf[a][1], 0.0f);
                    rr0[a].z = x0.z + fmaxf(accf[a][2], 0.0f);
                    rr0[a].w = x0.w + fmaxf(accf[a][3], 0.0f);
                    *reinterpret_cast<float4*>(outB + o) = rr0[a];
                    if (st2) {
                        const float4 x1 = *reinterpret_cast<const float4*>(xr + 4);
                        rr1[a].x = x1.x + fmaxf(accf[a][4], 0.0f);
                        rr1[a].y = x1.y + fmaxf(accf[a][5], 0.0f);
                        rr1[a].z = x1.z + fmaxf(accf[a][6], 0.0f);
                        rr1[a].w = x1.w + fmaxf(accf[a][7], 0.0f);
                        *reinterpret_cast<float4*>(outB + o + 4) = rr1[a];
                    }
                }
            }

            // prefetch next step's skip-connection row BEFORE the barrier
            float4 xn[NX];
            if (step + 1 < S) {
                #pragma unroll
                for (int it = 0; it < NX; ++it) {
                    int idx = tid + it * BLOCK;
                    if (idx < 32 * L4) {
                        int c = idx / L4, j = idx - c * L4;
                        xn[it] = *reinterpret_cast<const float4*>(
                            inB + (size_t)(co0 + c) * CHS + (size_t)pn * L + 4 * j);
                    }
                }
            }

            cluster_sync();   // release our slice, wait for peers

            // own 32 channels: store straight from registers (no L2 trip)
            if (wb) {
                #pragma unroll
                for (int a = 0; a < 4; ++a) {
                    const int c = co0 + colB + a;
                    float* dst = &pp[PP_OFF(c) + 4 + w0];
                    *reinterpret_cast<float4*>(dst) = rr0[a];
                    if (st2) *reinterpret_cast<float4*>(dst + 4) = rr1[a];
                }
            }
            // peers' 96 channels: reload just-written out row p via L2
            for (int idx = tid; idx < 96 * L4; idx += BLOCK) {
                int ch = idx / L4, j = idx - ch * L4;
                int c  = (co0 + 32 + ch) & (C_ - 1);
                const float4 v = __ldcg(reinterpret_cast<const float4*>(
                    outB + (size_t)c * CHS + rowOff + 4 * j));
                *reinterpret_cast<float4*>(&pp[PP_OFF(c) + 4 + 4 * j]) = v;
            }
            // commit the prefetched skip-connection row
            if (step + 1 < S) {
                #pragma unroll
                for (int it = 0; it < NX; ++it) {
                    int idx = tid + it * BLOCK;
                    if (idx < 32 * L4) {
                        int c = idx / L4, j = idx - c * L4;
                        *reinterpret_cast<float4*>(&xsm[c * L + 4 * j]) = xn[it];
                    }
                }
            }
            __syncthreads();
        }
    }
    #undef PP_OFF
    #undef W_OFF
}

// [planes][Y][X] -> [planes][X][Y]
__global__ void transpose_k(const float* __restrict__ in, float* __restrict__ out,
                            int Y, int X)
{
    __shared__ float t[32][33];
    const size_t plane = (size_t)blockIdx.z * Y * X;
    const float* ip = in + plane;
    float*       op = out + plane;
    const int x0 = blockIdx.x * 32, y0 = blockIdx.y * 32;
    #pragma unroll
    for (int dy = threadIdx.y; dy < 32; dy += 8) {
        const int x = x0 + threadIdx.x, y = y0 + dy;
        if (x < X && y < Y) t[dy][threadIdx.x] = ip[(size_t)y * X + x];
    }
    __syncthreads();
    #pragma unroll
    for (int dy = threadIdx.y; dy < 32; dy += 8) {
        const int xo = y0 + threadIdx.x, yo = x0 + dy;
        if (xo < Y && yo < X) op[(size_t)yo * Y + xo] = t[threadIdx.x][dy];
    }
}

extern "C" void kernel_launch(void* const* d_in, const int* in_sizes, int n_in,
                              void* d_out, int out_size)
{
    const float* x    = (const float*)d_in[0];
    const float* w_ud = (const float*)d_in[1];
    const float* w_du = (const float*)d_in[2];
    const float* w_lr = (const float*)d_in[3];
    const float* w_rl = (const float*)d_in[4];
    float* out = (float*)d_out;

    float *b0, *b1;
    cudaGetSymbolAddress((void**)&b0, g_buf0);
    cudaGetSymbolAddress((void**)&b1, g_buf1);

    constexpr int WROW = KW * 32;
    constexpr int WBLK = 16 * WROW + 32;
    constexpr int WFL  = 8 * WBLK + 32;
    constexpr int SM_V = (WFL + 8 * (16 * (W_ + 16) + 32) + 32 + 32 * W_) * 4;
    constexpr int SM_H = (WFL + 8 * (16 * (H_ + 16) + 32) + 32 + 32 * H_) * 4;

    // vertical: 13 w8-tiles x 8 cot x 4-way ci split = 416 thr (13 warps)
    // horizontal: 5 w8-tiles x 8 cot x 8-way ci split = 320 thr (10 warps)
    cudaFuncSetAttribute(scnn_pass<H_, W_, 4, 416>,
                         cudaFuncAttributeMaxDynamicSharedMemorySize, SM_V);
    cudaFuncSetAttribute(scnn_pass<W_, H_, 8, 320>,
                         cudaFuncAttributeMaxDynamicSharedMemorySize, SM_H);

    const dim3 grid(4, B_, 1);

    // pass 1: down  (scan H, conv along W), layout [B,C,H,W]
    scnn_pass<H_, W_, 4, 416><<<grid, 416, SM_V>>>(x,  w_ud, b0, 0);
    // pass 2: up
    scnn_pass<H_, W_, 4, 416><<<grid, 416, SM_V>>>(b0, w_du, b1, 1);
    // transpose HW -> WH so horizontal rows become contiguous
    transpose_k<<<dim3((W_ + 31) / 32, (H_ + 31) / 32, B_ * C_), dim3(32, 8)>>>(
        b1, b0, H_, W_);
    // pass 3: left->right (scan W, conv along H), layout [B,C,W,H]
    scnn_pass<W_, H_, 8, 320><<<grid, 320, SM_H>>>(b0, w_lr, b1, 0);
    // pass 4: right->left
    scnn_pass<W_, H_, 8, 320><<<grid, 320, SM_H>>>(b1, w_rl, b0, 1);
    // transpose back WH -> HW into the output buffer
    transpose_k<<<dim3((H_ + 31) / 32, (W_ + 31) / 32, B_ * C_), dim3(32, 8)>>>(
        b0, out, W_, H_);
}

// round 13
// speedup vs baseline: 1.0294x; 1.0294x over previous
#include <cuda_runtime.h>
#include <cstdint>

// Problem constants
#define B_  32
#define C_  128
#define H_  36
#define W_  100
#define KW  9

// Scratch ping-pong buffers (device globals: no runtime allocation allowed)
__device__ float g_buf0[(size_t)B_ * C_ * H_ * W_];
__device__ float g_buf1[(size_t)B_ * C_ * H_ * W_];

static __device__ __forceinline__ void cluster_sync() {
    asm volatile("barrier.cluster.arrive.aligned;" ::: "memory");
    asm volatile("barrier.cluster.wait.aligned;" ::: "memory");
}

// Per-16-ci-block skew (in floats). Quad permutation makes every
// 8-lane phase hit distinct 16B bank quads for the ciq-based lane maps.
// SKF is NON-monotonic in u, so every block gets a 32-float stride pad
// (WBLK/PBLK below) — without it adjacent blocks' regions overlap.
static __device__ __host__ __forceinline__ int SKF(int u) {
    return ((u & 1) << 3) + (((u >> 1) & 1) << 2) + ((u >> 2) << 4);
}

#define FMA2(d, a, b, c) \
    asm("fma.rn.f32x2 %0, %1, %2, %3;" : "=l"(d) : "l"(a), "l"(b), "l"(c))
#define PACK2(d, v) \
    asm("mov.b64 %0, {%1, %1};" : "=l"(d) : "f"(v))
#define UNPACK2(lo, hi, p) \
    asm("mov.b64 {%0, %1}, %2;" : "=f"(lo), "=f"(hi) : "l"(p))

// One SCNN message-passing pass over a [B, C, S, L] tensor:
// scan over dim 2 (length S), 1D conv (K=9, pad 4) along contiguous dim 3.
// Cluster of 4 CTAs per batch; CTA g owns output channels [32g, 32g+32).
// Weights live in SMEM all pass. Each thread: COW co x 8 w outputs.
// ci loop in 16-blocks with skewed+padded smem addressing, pipelined p
// loads, pre-barrier x prefetch, post-barrier own-slice STS.
template <int S, int L, int CI_SPLIT, int BLOCK, int COW>
__global__ void __launch_bounds__(BLOCK, 1) __cluster_dims__(4, 1, 1)
scnn_pass(const float* __restrict__ in, const float* __restrict__ wts,
          float* __restrict__ out, int rev)
{
    constexpr int PS    = L + 16;        // padded row stride (4 left, 12 right)
    constexpr int L4    = L / 4;
    constexpr int NWT   = (L + 7) / 8;   // 8-wide w tiles (last may be partial)
    constexpr int CHS   = S * L;
    constexpr int CIN   = C_ / CI_SPLIT;
    constexpr int NBLK  = CIN / 16;      // 16-ci blocks per thread
    constexpr int NPAIR = COW / 2;       // f32x2 co-pairs per thread
    constexpr int WROW  = KW * 32;       // floats per ci in weight smem
    constexpr int WBLK  = 16 * WROW + 32;// weight block stride (pad > max SKF)
    constexpr int PBLK  = 16 * PS + 32;  // p-row block stride
    constexpr int WFL   = 8 * WBLK + 32;
    constexpr int PPF   = 8 * PBLK + 32;
    constexpr int NX    = (32 * L4 + BLOCK - 1) / BLOCK;  // xsm staging iters

    extern __shared__ float smem[];
    float* wsm = smem;            // [blk pad+skew][ci16][k][co32]
    float* pp  = smem + WFL;      // [blk pad+skew][c16][PS]
    float* xsm = pp + PPF;        // [32 co][L] staged skip-connection row

    const int tid = threadIdx.x;
    const int g   = blockIdx.x;
    const int b   = blockIdx.y;
    const int co0 = g * 32;

    const float* inB  = in  + (size_t)b * C_ * CHS;
    float*       outB = out + (size_t)b * C_ * CHS;

    uint32_t sbase;
    asm("{ .reg .u64 t; cvta.to.shared.u64 t, %1; cvt.u32.u64 %0, t; }"
        : "=r"(sbase) : "l"(smem));

    #define PP_OFF(c)  (((c) >> 4) * PBLK + ((c) & 15) * PS + SKF((c) >> 4))
    #define W_OFF(ci)  (((ci) >> 4) * WBLK + ((ci) & 15) * WROW + SKF((ci) >> 4))

    // ---- load weight slice w[co0..co0+31][ci][k] into skewed smem ----
    {
        const float* wg = wts + (size_t)co0 * (C_ * KW);
        for (int idx = tid; idx < 32 * C_ * KW; idx += BLOCK) {
            int col = idx / (C_ * KW);
            int r   = idx - col * (C_ * KW);      // ci*9 + k
            int ci  = r / KW;
            int k   = r - ci * KW;
            wsm[W_OFF(ci) + k * 32 + col] = wg[idx];
        }
    }
    for (int idx = tid; idx < PPF; idx += BLOCK) pp[idx] = 0.0f;

    // ---- thread -> (COW co) x (8 consecutive w), ci split ----
    const int  task = tid / CI_SPLIT;
    const int  ciq  = tid % CI_SPLIT;
    const int  wt   = task % NWT;
    const int  cot  = task / NWT;        // 0 .. 32/COW-1 (exact task count)
    const int  w0   = wt * 8;
    const int  colB = cot * COW;
    const int  ci0  = ciq * CIN;
    const bool wb   = (ciq == 0);        // writer thread for this tile
    const bool st2  = (w0 + 4 < L);      // second float4 in range?

    __syncthreads();

    for (int step = 0; step < S; ++step) {
        const int    p      = rev ? (S - 1 - step) : step;
        const size_t rowOff = (size_t)p * L;
        const int    pn     = rev ? (p - 1) : (p + 1);   // next step's row

        if (step == 0) {
            for (int idx = tid; idx < 32 * L4; idx += BLOCK) {
                int c = idx / L4, j = idx - c * L4;
                const size_t o = (size_t)(co0 + c) * CHS + rowOff + 4 * j;
                *reinterpret_cast<float4*>(outB + o) =
                    *reinterpret_cast<const float4*>(inB + o);
            }
            for (int idx = tid; idx < C_ * L4; idx += BLOCK) {
                int c = idx / L4, j = idx - c * L4;
                const float4 v = *reinterpret_cast<const float4*>(
                    inB + (size_t)c * CHS + rowOff + 4 * j);
                *reinterpret_cast<float4*>(&pp[PP_OFF(c) + 4 + 4 * j]) = v;
            }
            #pragma unroll
            for (int it = 0; it < NX; ++it) {
                int idx = tid + it * BLOCK;
                if (idx < 32 * L4) {
                    int c = idx / L4, j = idx - c * L4;
                    *reinterpret_cast<float4*>(&xsm[c * L + 4 * j]) =
                        *reinterpret_cast<const float4*>(
                            inB + (size_t)(co0 + c) * CHS + (size_t)pn * L + 4 * j);
                }
            }
            __syncthreads();
        } else {
            unsigned long long acc2[NPAIR][8];
            #pragma unroll
            for (int pr = 0; pr < NPAIR; ++pr)
                #pragma unroll
                for (int j = 0; j < 8; ++j) acc2[pr][j] = 0ull;

            #pragma unroll
            for (int blk = 0; blk < NBLK; ++blk) {
                const int ub = (ci0 >> 4) + blk;     // 16-ci block index
                const float* prow = pp + ub * PBLK + SKF(ub) + w0;
                uint32_t     wadr = sbase +
                    (uint32_t)(ub * WBLK + SKF(ub) + colB) * 4u;

                // prime the p pipeline for this block
                float4 va = *reinterpret_cast<const float4*>(prow);
                float4 vb = *reinterpret_cast<const float4*>(prow + 4);
                float4 vc = *reinterpret_cast<const float4*>(prow + 8);
                float4 vd = *reinterpret_cast<const float4*>(prow + 12);

                #pragma unroll 2
                for (int i = 0; i < 16; ++i) {
                    unsigned long long vp[16];
                    PACK2(vp[0],  va.x); PACK2(vp[1],  va.y);
                    PACK2(vp[2],  va.z); PACK2(vp[3],  va.w);
                    PACK2(vp[4],  vb.x); PACK2(vp[5],  vb.y);
                    PACK2(vp[6],  vb.z); PACK2(vp[7],  vb.w);
                    PACK2(vp[8],  vc.x); PACK2(vp[9],  vc.y);
                    PACK2(vp[10], vc.z); PACK2(vp[11], vc.w);
                    PACK2(vp[12], vd.x); PACK2(vp[13], vd.y);
                    PACK2(vp[14], vd.z); PACK2(vp[15], vd.w);

                    // prefetch next i's p row during the FMA block
                    prow += PS;
                    if (i < 15) {
                        va = *reinterpret_cast<const float4*>(prow);
                        vb = *reinterpret_cast<const float4*>(prow + 4);
                        vc = *reinterpret_cast<const float4*>(prow + 8);
                        vd = *reinterpret_cast<const float4*>(prow + 12);
                    }

                    #pragma unroll
                    for (int k = 0; k < KW; ++k) {
                        if (NPAIR == 2) {
                            unsigned long long w01, w23;
                            asm("ld.shared.v2.b64 {%0, %1}, [%2];"
                                : "=l"(w01), "=l"(w23)
                                : "r"(wadr + (uint32_t)(k * 128)));
                            #pragma unroll
                            for (int j = 0; j < 8; ++j) {
                                FMA2(acc2[0][j], w01, vp[j + k], acc2[0][j]);
                                FMA2(acc2[1][j], w23, vp[j + k], acc2[1][j]);
                            }
                        } else {
                            unsigned long long w01;
                            asm("ld.shared.b64 %0, [%1];"
                                : "=l"(w01)
                                : "r"(wadr + (uint32_t)(k * 128)));
                            #pragma unroll
                            for (int j = 0; j < 8; ++j)
                                FMA2(acc2[0][j], w01, vp[j + k], acc2[0][j]);
                        }
                    }
                    wadr += WROW * 4;
                }
            }

            // unpack packed accumulators -> accf[a = co offset][j]
            float accf[COW][8];
            #pragma unroll
            for (int pr = 0; pr < NPAIR; ++pr)
                #pragma unroll
                for (int j = 0; j < 8; ++j)
                    UNPACK2(accf[2 * pr][j], accf[2 * pr + 1][j], acc2[pr][j]);

            if (CI_SPLIT > 1) {                      // reduce across ciq lanes
                #pragma unroll
                for (int a = 0; a < COW; ++a)
                    #pragma unroll
                    for (int j = 0; j < 8; ++j) {
                        float s = accf[a][j];
                        #pragma unroll
                        for (int off = CI_SPLIT >> 1; off > 0; off >>= 1)
                            s += __shfl_down_sync(0xffffffffu, s, off);
                        accf[a][j] = s;
                    }
            }

            // finalize own rows; store to gmem, keep for post-barrier STS
            float4 rr0[COW], rr1[COW];
            if (wb) {
                #pragma unroll
                for (int a = 0; a < COW; ++a) {
                    const float* xr = &xsm[(colB + a) * L + w0];
                    const size_t o  = (size_t)(co0 + colB + a) * CHS + rowOff + w0;
                    const float4 x0 = *reinterpret_cast<const float4*>(xr);
                    rr0[a].x = x0.x + fmaxf(accf[a][0], 0.0f);
                    rr0[a].y = x0.y + fmaxf(accf[a][1], 0.0f);
                    rr0[a].z = x0.z + fmaxf(accf[a][2], 0.0f);
                    rr0[a].w = x0.w + fmaxf(accf[a][3], 0.0f);
                    *reinterpret_cast<float4*>(outB + o) = rr0[a];
                    if (st2) {
                        const float4 x1 = *reinterpret_cast<const float4*>(xr + 4);
                        rr1[a].x = x1.x + fmaxf(accf[a][4], 0.0f);
                        rr1[a].y = x1.y + fmaxf(accf[a][5], 0.0f);
                        rr1[a].z = x1.z + fmaxf(accf[a][6], 0.0f);
                        rr1[a].w = x1.w + fmaxf(accf[a][7], 0.0f);
                        *reinterpret_cast<float4*>(outB + o + 4) = rr1[a];
                    }
                }
            }

            // prefetch next step's skip-connection row BEFORE the barrier
            float4 xn[NX];
            if (step + 1 < S) {
                #pragma unroll
                for (int it = 0; it < NX; ++it) {
                    int idx = tid + it * BLOCK;
                    if (idx < 32 * L4) {
                        int c = idx / L4, j = idx - c * L4;
                        xn[it] = *reinterpret_cast<const float4*>(
                            inB + (size_t)(co0 + c) * CHS + (size_t)pn * L + 4 * j);
                    }
                }
            }

            cluster_sync();   // release our slice, wait for peers

            // own 32 channels: store straight from registers (no L2 trip)
            if (wb) {
                #pragma unroll
                for (int a = 0; a < COW; ++a) {
                    const int c = co0 + colB + a;
                    float* dst = &pp[PP_OFF(c) + 4 + w0];
                    *reinterpret_cast<float4*>(dst) = rr0[a];
                    if (st2) *reinterpret_cast<float4*>(dst + 4) = rr1[a];
                }
            }
            // peers' 96 channels: reload just-written out row p via L2
            for (int idx = tid; idx < 96 * L4; idx += BLOCK) {
                int ch = idx / L4, j = idx - ch * L4;
                int c  = (co0 + 32 + ch) & (C_ - 1);
                const float4 v = __ldcg(reinterpret_cast<const float4*>(
                    outB + (size_t)c * CHS + rowOff + 4 * j));
                *reinterpret_cast<float4*>(&pp[PP_OFF(c) + 4 + 4 * j]) = v;
            }
            // commit the prefetched skip-connection row
            if (step + 1 < S) {
                #pragma unroll
                for (int it = 0; it < NX; ++it) {
                    int idx = tid + it * BLOCK;
                    if (idx < 32 * L4) {
                        int c = idx / L4, j = idx - c * L4;
                        *reinterpret_cast<float4*>(&xsm[c * L + 4 * j]) = xn[it];
                    }
                }
            }
            __syncthreads();
        }
    }
    #undef PP_OFF
    #undef W_OFF
}

// [planes][Y][X] -> [planes][X][Y]
__global__ void transpose_k(const float* __restrict__ in, float* __restrict__ out,
                            int Y, int X)
{
    __shared__ float t[32][33];
    const size_t plane = (size_t)blockIdx.z * Y * X;
    const float* ip = in + plane;
    float*       op = out + plane;
    const int x0 = blockIdx.x * 32, y0 = blockIdx.y * 32;
    #pragma unroll
    for (int dy = threadIdx.y; dy < 32; dy += 8) {
        const int x = x0 + threadIdx.x, y = y0 + dy;
        if (x < X && y < Y) t[dy][threadIdx.x] = ip[(size_t)y * X + x];
    }
    __syncthreads();
    #pragma unroll
    for (int dy = threadIdx.y; dy < 32; dy += 8) {
        const int xo = y0 + threadIdx.x, yo = x0 + dy;
        if (xo < Y && yo < X) op[(size_t)yo * Y + xo] = t[threadIdx.x][dy];
    }
}

extern "C" void kernel_launch(void* const* d_in, const int* in_sizes, int n_in,
                              void* d_out, int out_size)
{
    const float* x    = (const float*)d_in[0];
    const float* w_ud = (const float*)d_in[1];
    const float* w_du = (const float*)d_in[2];
    const float* w_lr = (const float*)d_in[3];
    const float* w_rl = (const float*)d_in[4];
    float* out = (float*)d_out;

    float *b0, *b1;
    cudaGetSymbolAddress((void**)&b0, g_buf0);
    cudaGetSymbolAddress((void**)&b1, g_buf1);

    constexpr int WROW = KW * 32;
    constexpr int WBLK = 16 * WROW + 32;
    constexpr int WFL  = 8 * WBLK + 32;
    constexpr int SM_V = (WFL + 8 * (16 * (W_ + 16) + 32) + 32 + 32 * W_) * 4;
    constexpr int SM_H = (WFL + 8 * (16 * (H_ + 16) + 32) + 32 + 32 * H_) * 4;

    // vertical: co4 x w8: 13 wt x 8 cot x 4 ciq = 416 thr (13 warps)
    // horizontal: co2 x w8: 5 wt x 16 cot x 8 ciq = 640 thr (20 warps)
    cudaFuncSetAttribute(scnn_pass<H_, W_, 4, 416, 4>,
                         cudaFuncAttributeMaxDynamicSharedMemorySize, SM_V);
    cudaFuncSetAttribute(scnn_pass<W_, H_, 8, 640, 2>,
                         cudaFuncAttributeMaxDynamicSharedMemorySize, SM_H);

    const dim3 grid(4, B_, 1);

    // pass 1: down  (scan H, conv along W), layout [B,C,H,W]
    scnn_pass<H_, W_, 4, 416, 4><<<grid, 416, SM_V>>>(x,  w_ud, b0, 0);
    // pass 2: up
    scnn_pass<H_, W_, 4, 416, 4><<<grid, 416, SM_V>>>(b0, w_du, b1, 1);
    // transpose HW -> WH so horizontal rows become contiguous
    transpose_k<<<dim3((W_ + 31) / 32, (H_ + 31) / 32, B_ * C_), dim3(32, 8)>>>(
        b1, b0, H_, W_);
    // pass 3: left->right (scan W, conv along H), layout [B,C,W,H]
    scnn_pass<W_, H_, 8, 640, 2><<<grid, 640, SM_H>>>(b0, w_lr, b1, 0);
    // pass 4: right->left
    scnn_pass<W_, H_, 8, 640, 2><<<grid, 640, SM_H>>>(b1, w_rl, b0, 1);
    // transpose back WH -> HW into the output buffer
    transpose_k<<<dim3((H_ + 31) / 32, (W_ + 31) / 32, B_ * C_), dim3(32, 8)>>>(
        b0, out, W_, H_);
}

// round 14
// speedup vs baseline: 1.0937x; 1.0625x over previous
#include <cuda_runtime.h>
#include <cstdint>

// Problem constants
#define B_  32
#define C_  128
#define H_  36
#define W_  100
#define KW  9

// Scratch ping-pong buffers (device globals: no runtime allocation allowed)
__device__ float g_buf0[(size_t)B_ * C_ * H_ * W_];
__device__ float g_buf1[(size_t)B_ * C_ * H_ * W_];

static __device__ __forceinline__ void cluster_sync() {
    asm volatile("barrier.cluster.arrive.aligned;" ::: "memory");
    asm volatile("barrier.cluster.wait.aligned;" ::: "memory");
}

// Per-16-ci-block skew (in floats). Quad map Q(u) = ((u>>1)&1) + 4*(u>>2)
// + 2*(u&1) guarantees Q(ub) + 2*wt distinct within every LDS phase for
// BOTH lane mappings (vertical: 2 tasks x 4 ciq; horizontal: 8 ciq).
// Non-monotonic -> every block carries a 32-float stride pad (WBLK/PBLK).
static __device__ __host__ __forceinline__ int SKF(int u) {
    return (((u >> 1) & 1) << 2) + ((u >> 2) << 4) + ((u & 1) << 3);
}

#define FMA2(d, a, b, c) \
    asm("fma.rn.f32x2 %0, %1, %2, %3;" : "=l"(d) : "l"(a), "l"(b), "l"(c))
#define PACK2(d, v) \
    asm("mov.b64 %0, {%1, %1};" : "=l"(d) : "f"(v))
#define UNPACK2(lo, hi, p) \
    asm("mov.b64 {%0, %1}, %2;" : "=f"(lo), "=f"(hi) : "l"(p))

// One SCNN message-passing pass over a [B, C, S, L] tensor:
// scan over dim 2 (length S), 1D conv (K=9, pad 4) along contiguous dim 3.
// Cluster of 4 CTAs per batch; CTA g owns output channels [32g, 32g+32).
// Weights live in SMEM all pass. Each thread: COW co x 8 w outputs.
// ci loop in 16-blocks with skewed+padded smem addressing, pipelined p
// loads, pre-barrier x prefetch, post-barrier own-slice STS.
template <int S, int L, int CI_SPLIT, int BLOCK, int COW>
__global__ void __launch_bounds__(BLOCK, 1) __cluster_dims__(4, 1, 1)
scnn_pass(const float* __restrict__ in, const float* __restrict__ wts,
          float* __restrict__ out, int rev)
{
    constexpr int PS    = L + 16;        // padded row stride (4 left, 12 right)
    constexpr int L4    = L / 4;
    constexpr int NWT   = (L + 7) / 8;   // 8-wide w tiles (last may be partial)
    constexpr int CHS   = S * L;
    constexpr int CIN   = C_ / CI_SPLIT;
    constexpr int NBLK  = CIN / 16;      // 16-ci blocks per thread
    constexpr int NPAIR = COW / 2;       // f32x2 co-pairs per thread
    constexpr int WROW  = KW * 32;       // floats per ci in weight smem
    constexpr int WBLK  = 16 * WROW + 32;// weight block stride (pad > max SKF)
    constexpr int PBLK  = 16 * PS + 32;  // p-row block stride
    constexpr int WFL   = 8 * WBLK + 32;
    constexpr int PPF   = 8 * PBLK + 32;
    constexpr int NX    = (32 * L4 + BLOCK - 1) / BLOCK;  // xsm staging iters

    extern __shared__ float smem[];
    float* wsm = smem;            // [blk pad+skew][ci16][k][co32]
    float* pp  = smem + WFL;      // [blk pad+skew][c16][PS]
    float* xsm = pp + PPF;        // [32 co][L] staged skip-connection row

    const int tid = threadIdx.x;
    const int g   = blockIdx.x;
    const int b   = blockIdx.y;
    const int co0 = g * 32;

    const float* inB  = in  + (size_t)b * C_ * CHS;
    float*       outB = out + (size_t)b * C_ * CHS;

    uint32_t sbase;
    asm("{ .reg .u64 t; cvta.to.shared.u64 t, %1; cvt.u32.u64 %0, t; }"
        : "=r"(sbase) : "l"(smem));

    #define PP_OFF(c)  (((c) >> 4) * PBLK + ((c) & 15) * PS + SKF((c) >> 4))
    #define W_OFF(ci)  (((ci) >> 4) * WBLK + ((ci) & 15) * WROW + SKF((ci) >> 4))

    // ---- load weight slice w[co0..co0+31][ci][k] into skewed smem ----
    {
        const float* wg = wts + (size_t)co0 * (C_ * KW);
        for (int idx = tid; idx < 32 * C_ * KW; idx += BLOCK) {
            int col = idx / (C_ * KW);
            int r   = idx - col * (C_ * KW);      // ci*9 + k
            int ci  = r / KW;
            int k   = r - ci * KW;
            wsm[W_OFF(ci) + k * 32 + col] = wg[idx];
        }
    }
    for (int idx = tid; idx < PPF; idx += BLOCK) pp[idx] = 0.0f;

    // ---- thread -> (COW co) x (8 consecutive w), ci split ----
    const int  task = tid / CI_SPLIT;
    const int  ciq  = tid % CI_SPLIT;
    const int  wt   = task % NWT;
    const int  cot  = task / NWT;        // 0 .. 32/COW-1 (exact task count)
    const int  w0   = wt * 8;
    const int  colB = cot * COW;
    const int  ci0  = ciq * CIN;
    const bool wb   = (ciq == 0);        // writer thread for this tile
    const bool st2  = (w0 + 4 < L);      // second float4 in range?

    __syncthreads();

    for (int step = 0; step < S; ++step) {
        const int    p      = rev ? (S - 1 - step) : step;
        const size_t rowOff = (size_t)p * L;
        const int    pn     = rev ? (p - 1) : (p + 1);   // next step's row

        if (step == 0) {
            for (int idx = tid; idx < 32 * L4; idx += BLOCK) {
                int c = idx / L4, j = idx - c * L4;
                const size_t o = (size_t)(co0 + c) * CHS + rowOff + 4 * j;
                *reinterpret_cast<float4*>(outB + o) =
                    *reinterpret_cast<const float4*>(inB + o);
            }
            for (int idx = tid; idx < C_ * L4; idx += BLOCK) {
                int c = idx / L4, j = idx - c * L4;
                const float4 v = *reinterpret_cast<const float4*>(
                    inB + (size_t)c * CHS + rowOff + 4 * j);
                *reinterpret_cast<float4*>(&pp[PP_OFF(c) + 4 + 4 * j]) = v;
            }
            #pragma unroll
            for (int it = 0; it < NX; ++it) {
                int idx = tid + it * BLOCK;
                if (idx < 32 * L4) {
                    int c = idx / L4, j = idx - c * L4;
                    *reinterpret_cast<float4*>(&xsm[c * L + 4 * j]) =
                        *reinterpret_cast<const float4*>(
                            inB + (size_t)(co0 + c) * CHS + (size_t)pn * L + 4 * j);
                }
            }
            __syncthreads();
        } else {
            unsigned long long acc2[NPAIR][8];
            #pragma unroll
            for (int pr = 0; pr < NPAIR; ++pr)
                #pragma unroll
                for (int j = 0; j < 8; ++j) acc2[pr][j] = 0ull;

            #pragma unroll
            for (int blk = 0; blk < NBLK; ++blk) {
                const int ub = (ci0 >> 4) + blk;     // 16-ci block index
                const float* prow = pp + ub * PBLK + SKF(ub) + w0;
                uint32_t     wadr = sbase +
                    (uint32_t)(ub * WBLK + SKF(ub) + colB) * 4u;

                // prime the p pipeline for this block
                float4 va = *reinterpret_cast<const float4*>(prow);
                float4 vb = *reinterpret_cast<const float4*>(prow + 4);
                float4 vc = *reinterpret_cast<const float4*>(prow + 8);
                float4 vd = *reinterpret_cast<const float4*>(prow + 12);

                #pragma unroll 2
                for (int i = 0; i < 16; ++i) {
                    unsigned long long vp[16];
                    PACK2(vp[0],  va.x); PACK2(vp[1],  va.y);
                    PACK2(vp[2],  va.z); PACK2(vp[3],  va.w);
                    PACK2(vp[4],  vb.x); PACK2(vp[5],  vb.y);
                    PACK2(vp[6],  vb.z); PACK2(vp[7],  vb.w);
                    PACK2(vp[8],  vc.x); PACK2(vp[9],  vc.y);
                    PACK2(vp[10], vc.z); PACK2(vp[11], vc.w);
                    PACK2(vp[12], vd.x); PACK2(vp[13], vd.y);
                    PACK2(vp[14], vd.z); PACK2(vp[15], vd.w);

                    // prefetch next i's p row during the FMA block
                    prow += PS;
                    if (i < 15) {
                        va = *reinterpret_cast<const float4*>(prow);
                        vb = *reinterpret_cast<const float4*>(prow + 4);
                        vc = *reinterpret_cast<const float4*>(prow + 8);
                        vd = *reinterpret_cast<const float4*>(prow + 12);
                    }

                    #pragma unroll
                    for (int k = 0; k < KW; ++k) {
                        if (NPAIR == 2) {
                            unsigned long long w01, w23;
                            asm("ld.shared.v2.b64 {%0, %1}, [%2];"
                                : "=l"(w01), "=l"(w23)
                                : "r"(wadr + (uint32_t)(k * 128)));
                            #pragma unroll
                            for (int j = 0; j < 8; ++j) {
                                FMA2(acc2[0][j], w01, vp[j + k], acc2[0][j]);
                                FMA2(acc2[1][j], w23, vp[j + k], acc2[1][j]);
                            }
                        } else {
                            unsigned long long w01;
                            asm("ld.shared.b64 %0, [%1];"
                                : "=l"(w01)
                                : "r"(wadr + (uint32_t)(k * 128)));
                            #pragma unroll
                            for (int j = 0; j < 8; ++j)
                                FMA2(acc2[0][j], w01, vp[j + k], acc2[0][j]);
                        }
                    }
                    wadr += WROW * 4;
                }
            }

            // unpack packed accumulators -> accf[a = co offset][j]
            float accf[COW][8];
            #pragma unroll
            for (int pr = 0; pr < NPAIR; ++pr)
                #pragma unroll
                for (int j = 0; j < 8; ++j)
                    UNPACK2(accf[2 * pr][j], accf[2 * pr + 1][j], acc2[pr][j]);

            if (CI_SPLIT > 1) {                      // reduce across ciq lanes
                #pragma unroll
                for (int a = 0; a < COW; ++a)
                    #pragma unroll
                    for (int j = 0; j < 8; ++j) {
                        float s = accf[a][j];
                        #pragma unroll
                        for (int off = CI_SPLIT >> 1; off > 0; off >>= 1)
                            s += __shfl_down_sync(0xffffffffu, s, off);
                        accf[a][j] = s;
                    }
            }

            // finalize own rows; store to gmem, keep for post-barrier STS
            float4 rr0[COW], rr1[COW];
            if (wb) {
                #pragma unroll
                for (int a = 0; a < COW; ++a) {
                    const float* xr = &xsm[(colB + a) * L + w0];
                    const size_t o  = (size_t)(co0 + colB + a) * CHS + rowOff + w0;
                    const float4 x0 = *reinterpret_cast<const float4*>(xr);
                    rr0[a].x = x0.x + fmaxf(accf[a][0], 0.0f);
                    rr0[a].y = x0.y + fmaxf(accf[a][1], 0.0f);
                    rr0[a].z = x0.z + fmaxf(accf[a][2], 0.0f);
                    rr0[a].w = x0.w + fmaxf(accf[a][3], 0.0f);
                    *reinterpret_cast<float4*>(outB + o) = rr0[a];
                    if (st2) {
                        const float4 x1 = *reinterpret_cast<const float4*>(xr + 4);
                        rr1[a].x = x1.x + fmaxf(accf[a][4], 0.0f);
                        rr1[a].y = x1.y + fmaxf(accf[a][5], 0.0f);
                        rr1[a].z = x1.z + fmaxf(accf[a][6], 0.0f);
                        rr1[a].w = x1.w + fmaxf(accf[a][7], 0.0f);
                        *reinterpret_cast<float4*>(outB + o + 4) = rr1[a];
                    }
                }
            }

            // prefetch next step's skip-connection row BEFORE the barrier
            float4 xn[NX];
            if (step + 1 < S) {
                #pragma unroll
                for (int it = 0; it < NX; ++it) {
                    int idx = tid + it * BLOCK;
                    if (idx < 32 * L4) {
                        int c = idx / L4, j = idx - c * L4;
                        xn[it] = *reinterpret_cast<const float4*>(
                            inB + (size_t)(co0 + c) * CHS + (size_t)pn * L + 4 * j);
                    }
                }
            }

            cluster_sync();   // release our slice, wait for peers

            // own 32 channels: store straight from registers (no L2 trip)
            if (wb) {
                #pragma unroll
                for (int a = 0; a < COW; ++a) {
                    const int c = co0 + colB + a;
                    float* dst = &pp[PP_OFF(c) + 4 + w0];
                    *reinterpret_cast<float4*>(dst) = rr0[a];
                    if (st2) *reinterpret_cast<float4*>(dst + 4) = rr1[a];
                }
            }
            // peers' 96 channels: reload just-written out row p via L2
            for (int idx = tid; idx < 96 * L4; idx += BLOCK) {
                int ch = idx / L4, j = idx - ch * L4;
                int c  = (co0 + 32 + ch) & (C_ - 1);
                const float4 v = __ldcg(reinterpret_cast<const float4*>(
                    outB + (size_t)c * CHS + rowOff + 4 * j));
                *reinterpret_cast<float4*>(&pp[PP_OFF(c) + 4 + 4 * j]) = v;
            }
            // commit the prefetched skip-connection row
            if (step + 1 < S) {
                #pragma unroll
                for (int it = 0; it < NX; ++it) {
                    int idx = tid + it * BLOCK;
                    if (idx < 32 * L4) {
                        int c = idx / L4, j = idx - c * L4;
                        *reinterpret_cast<float4*>(&xsm[c * L + 4 * j]) = xn[it];
                    }
                }
            }
            __syncthreads();
        }
    }
    #undef PP_OFF
    #undef W_OFF
}

// [planes][Y][X] -> [planes][X][Y]
__global__ void transpose_k(const float* __restrict__ in, float* __restrict__ out,
                            int Y, int X)
{
    __shared__ float t[32][33];
    const size_t plane = (size_t)blockIdx.z * Y * X;
    const float* ip = in + plane;
    float*       op = out + plane;
    const int x0 = blockIdx.x * 32, y0 = blockIdx.y * 32;
    #pragma unroll
    for (int dy = threadIdx.y; dy < 32; dy += 8) {
        const int x = x0 + threadIdx.x, y = y0 + dy;
        if (x < X && y < Y) t[dy][threadIdx.x] = ip[(size_t)y * X + x];
    }
    __syncthreads();
    #pragma unroll
    for (int dy = threadIdx.y; dy < 32; dy += 8) {
        const int xo = y0 + threadIdx.x, yo = x0 + dy;
        if (xo < Y && yo < X) op[(size_t)yo * Y + xo] = t[threadIdx.x][dy];
    }
}

extern "C" void kernel_launch(void* const* d_in, const int* in_sizes, int n_in,
                              void* d_out, int out_size)
{
    const float* x    = (const float*)d_in[0];
    const float* w_ud = (const float*)d_in[1];
    const float* w_du = (const float*)d_in[2];
    const float* w_lr = (const float*)d_in[3];
    const float* w_rl = (const float*)d_in[4];
    float* out = (float*)d_out;

    float *b0, *b1;
    cudaGetSymbolAddress((void**)&b0, g_buf0);
    cudaGetSymbolAddress((void**)&b1, g_buf1);

    constexpr int WROW = KW * 32;
    constexpr int WBLK = 16 * WROW + 32;
    constexpr int WFL  = 8 * WBLK + 32;
    constexpr int SM_V = (WFL + 8 * (16 * (W_ + 16) + 32) + 32 + 32 * W_) * 4;
    constexpr int SM_H = (WFL + 8 * (16 * (H_ + 16) + 32) + 32 + 32 * H_) * 4;

    // vertical:  co2 x w8: 13 wt x 16 cot x 4 ciq = 832 thr (26 warps)
    // horizontal: co2 x w8: 5 wt x 16 cot x 8 ciq = 640 thr (20 warps)
    cudaFuncSetAttribute(scnn_pass<H_, W_, 4, 832, 2>,
                         cudaFuncAttributeMaxDynamicSharedMemorySize, SM_V);
    cudaFuncSetAttribute(scnn_pass<W_, H_, 8, 640, 2>,
                         cudaFuncAttributeMaxDynamicSharedMemorySize, SM_H);

    const dim3 grid(4, B_, 1);

    // pass 1: down  (scan H, conv along W), layout [B,C,H,W]
    scnn_pass<H_, W_, 4, 832, 2><<<grid, 832, SM_V>>>(x,  w_ud, b0, 0);
    // pass 2: up
    scnn_pass<H_, W_, 4, 832, 2><<<grid, 832, SM_V>>>(b0, w_du, b1, 1);
    // transpose HW -> WH so horizontal rows become contiguous
    transpose_k<<<dim3((W_ + 31) / 32, (H_ + 31) / 32, B_ * C_), dim3(32, 8)>>>(
        b1, b0, H_, W_);
    // pass 3: left->right (scan W, conv along H), layout [B,C,W,H]
    scnn_pass<W_, H_, 8, 640, 2><<<grid, 640, SM_H>>>(b0, w_lr, b1, 0);
    // pass 4: right->left
    scnn_pass<W_, H_, 8, 640, 2><<<grid, 640, SM_H>>>(b1, w_rl, b0, 1);
    // transpose back WH -> HW into the output buffer
    transpose_k<<<dim3((H_ + 31) / 32, (W_ + 31) / 32, B_ * C_), dim3(32, 8)>>>(
        b0, out, W_, H_);
}

// round 16
// speedup vs baseline: 1.0997x; 1.0055x over previous
#include <cuda_runtime.h>
#include <cstdint>

// Problem constants
#define B_  32
#define C_  128
#define H_  36
#define W_  100
#define KW  9

// Scratch ping-pong buffers (device globals: no runtime allocation allowed)
__device__ float g_buf0[(size_t)B_ * C_ * H_ * W_];
__device__ float g_buf1[(size_t)B_ * C_ * H_ * W_];
__device__ float g_buf2[(size_t)B_ * C_ * H_ * W_];

#define CLUSTER_ARRIVE() \
    asm volatile("barrier.cluster.arrive.aligned;" ::: "memory")
#define CLUSTER_WAIT() \
    asm volatile("barrier.cluster.wait.aligned;" ::: "memory")

// Per-16-ci-block skew (in floats). Quad map Q(u) = ((u>>1)&1) + 4*(u>>2)
// + 2*(u&1) keeps Q(ub) + 2*wt distinct within every LDS phase for BOTH
// lane mappings (vertical: 2 tasks x 4 ciq; horizontal: 8 ciq).
// Non-monotonic -> every block carries a 32-float stride pad (WBLK/PBLK).
static __device__ __host__ __forceinline__ int SKF(int u) {
    return (((u >> 1) & 1) << 2) + ((u >> 2) << 4) + ((u & 1) << 3);
}

#define FMA2(d, a, b, c) \
    asm("fma.rn.f32x2 %0, %1, %2, %3;" : "=l"(d) : "l"(a), "l"(b), "l"(c))
#define PACK2(d, v) \
    asm("mov.b64 %0, {%1, %1};" : "=l"(d) : "f"(v))
#define UNPACK2(lo, hi, p) \
    asm("mov.b64 {%0, %1}, %2;" : "=f"(lo), "=f"(hi) : "l"(p))

// One SCNN message-passing pass over a [B, C, S, L] tensor:
// scan over dim 2 (length S), 1D conv (K=9, pad 4) along contiguous dim 3.
// Cluster of 4 CTAs per batch; CTA g owns output channels [32g, 32g+32).
// Weights live in SMEM all pass. Each thread: COW co x 8 w outputs.
// Butterfly ci-reduce spreads the epilogue across ciq lanes; the cluster
// barrier is split (arrive ... local work ... wait). If TRANS, the pass also
// emits a [B,C,L,S]-transposed copy of its output (fusing the transpose);
// transposed VALUES are computed pre-arrive (xsm stable), only the STGs are
// deferred under the barrier (avoids the xsm read/commit race).
template <int S, int L, int CI_SPLIT, int BLOCK, int COW, bool TRANS>
__global__ void __launch_bounds__(BLOCK, 1) __cluster_dims__(4, 1, 1)
scnn_pass(const float* __restrict__ in, const float* __restrict__ wts,
          float* __restrict__ out, int rev, float* __restrict__ tout)
{
    constexpr int PS    = L + 16;        // padded row stride (4 left, 12 right)
    constexpr int L4    = L / 4;
    constexpr int NWT   = (L + 7) / 8;   // 8-wide w tiles (last may be partial)
    constexpr int CHS   = S * L;
    constexpr int CIN   = C_ / CI_SPLIT;
    constexpr int NBLK  = CIN / 16;      // 16-ci blocks per thread
    constexpr int NPAIR = COW / 2;       // f32x2 co-pairs per thread
    constexpr int WROW  = KW * 32;       // floats per ci in weight smem
    constexpr int WBLK  = 16 * WROW + 32;// weight block stride (pad > max SKF)
    constexpr int PBLK  = 16 * PS + 32;  // p-row block stride
    constexpr int WFL   = 8 * WBLK + 32;
    constexpr int PPF   = 8 * PBLK + 32;
    constexpr int NX    = (32 * L4 + BLOCK - 1) / BLOCK;  // xsm staging iters

    extern __shared__ float smem[];
    float* wsm = smem;            // [blk pad+skew][ci16][k][co32]
    float* pp  = smem + WFL;      // [blk pad+skew][c16][PS]
    float* xsm = pp + PPF;        // [32 co][L] staged skip-connection row

    const int tid = threadIdx.x;
    const int g   = blockIdx.x;
    const int b   = blockIdx.y;
    const int co0 = g * 32;

    const float* inB  = in  + (size_t)b * C_ * CHS;
    float*       outB = out + (size_t)b * C_ * CHS;
    float*       toutB = TRANS ? tout + (size_t)b * C_ * CHS : nullptr;

    uint32_t sbase;
    asm("{ .reg .u64 t; cvta.to.shared.u64 t, %1; cvt.u32.u64 %0, t; }"
        : "=r"(sbase) : "l"(smem));

    #define PP_OFF(c)  (((c) >> 4) * PBLK + ((c) & 15) * PS + SKF((c) >> 4))
    #define W_OFF(ci)  (((ci) >> 4) * WBLK + ((ci) & 15) * WROW + SKF((ci) >> 4))

    // ---- load weight slice w[co0..co0+31][ci][k] into skewed smem ----
    {
        const float* wg = wts + (size_t)co0 * (C_ * KW);
        for (int idx = tid; idx < 32 * C_ * KW; idx += BLOCK) {
            int col = idx / (C_ * KW);
            int r   = idx - col * (C_ * KW);      // ci*9 + k
            int ci  = r / KW;
            int k   = r - ci * KW;
            wsm[W_OFF(ci) + k * 32 + col] = wg[idx];
        }
    }
    for (int idx = tid; idx < PPF; idx += BLOCK) pp[idx] = 0.0f;

    // ---- thread -> (COW co) x (8 consecutive w), ci split ----
    const int  task = tid / CI_SPLIT;
    const int  ciq  = tid % CI_SPLIT;
    const int  wt   = task % NWT;
    const int  cot  = task / NWT;        // 0 .. 32/COW-1 (exact task count)
    const int  w0   = wt * 8;
    const int  colB = cot * COW;
    const int  ci0  = ciq * CIN;
    const bool st2  = (w0 + 4 < L);      // second float4 in range?

    // epilogue roles: lane ciq = aa*2+hh writes float4 (co colB+aa, half hh)
    const int  aa   = ciq >> 1;
    const int  hh   = ciq & 1;
    const bool doO  = (ciq < 2 * COW) && (hh == 0 || st2);
    // transposed-writer lane: spare lanes 4..7 when CI_SPLIT>=8, else 0..3
    const int  tl   = (CI_SPLIT >= 8) ? (ciq - 4) : ciq;
    const bool doT  = TRANS && (tl >= 0) && (tl < 4);

    __syncthreads();

    for (int step = 0; step < S; ++step) {
        const int    p      = rev ? (S - 1 - step) : step;
        const size_t rowOff = (size_t)p * L;
        const int    pn     = rev ? (p - 1) : (p + 1);   // next step's row

        if (step == 0) {
            for (int idx = tid; idx < 32 * L4; idx += BLOCK) {
                int c = idx / L4, j = idx - c * L4;
                const size_t o = (size_t)(co0 + c) * CHS + rowOff + 4 * j;
                *reinterpret_cast<float4*>(outB + o) =
                    *reinterpret_cast<const float4*>(inB + o);
            }
            if (TRANS) {   // transposed copy of row p (own co slice)
                for (int idx = tid; idx < 32 * L; idx += BLOCK) {
                    int c = idx / L, w = idx - c * L;
                    toutB[(size_t)(co0 + c) * CHS + (size_t)w * S + p] =
                        inB[(size_t)(co0 + c) * CHS + rowOff + w];
                }
            }
            for (int idx = tid; idx < C_ * L4; idx += BLOCK) {
                int c = idx / L4, j = idx - c * L4;
                const float4 v = *reinterpret_cast<const float4*>(
                    inB + (size_t)c * CHS + rowOff + 4 * j);
                *reinterpret_cast<float4*>(&pp[PP_OFF(c) + 4 + 4 * j]) = v;
            }
            #pragma unroll
            for (int it = 0; it < NX; ++it) {
                int idx = tid + it * BLOCK;
                if (idx < 32 * L4) {
                    int c = idx / L4, j = idx - c * L4;
                    *reinterpret_cast<float4*>(&xsm[c * L + 4 * j]) =
                        *reinterpret_cast<const float4*>(
                            inB + (size_t)(co0 + c) * CHS + (size_t)pn * L + 4 * j);
                }
            }
            __syncthreads();
        } else {
            unsigned long long acc2[NPAIR][8];
            #pragma unroll
            for (int pr = 0; pr < NPAIR; ++pr)
                #pragma unroll
                for (int j = 0; j < 8; ++j) acc2[pr][j] = 0ull;

            #pragma unroll
            for (int blk = 0; blk < NBLK; ++blk) {
                const int ub = (ci0 >> 4) + blk;     // 16-ci block index
                const float* prow = pp + ub * PBLK + SKF(ub) + w0;
                uint32_t     wadr = sbase +
                    (uint32_t)(ub * WBLK + SKF(ub) + colB) * 4u;

                // prime the p pipeline for this block
                float4 va = *reinterpret_cast<const float4*>(prow);
                float4 vb = *reinterpret_cast<const float4*>(prow + 4);
                float4 vc = *reinterpret_cast<const float4*>(prow + 8);
                float4 vd = *reinterpret_cast<const float4*>(prow + 12);

                #pragma unroll 2
                for (int i = 0; i < 16; ++i) {
                    unsigned long long vp[16];
                    PACK2(vp[0],  va.x); PACK2(vp[1],  va.y);
                    PACK2(vp[2],  va.z); PACK2(vp[3],  va.w);
                    PACK2(vp[4],  vb.x); PACK2(vp[5],  vb.y);
                    PACK2(vp[6],  vb.z); PACK2(vp[7],  vb.w);
                    PACK2(vp[8],  vc.x); PACK2(vp[9],  vc.y);
                    PACK2(vp[10], vc.z); PACK2(vp[11], vc.w);
                    PACK2(vp[12], vd.x); PACK2(vp[13], vd.y);
                    PACK2(vp[14], vd.z); PACK2(vp[15], vd.w);

                    // prefetch next i's p row during the FMA block
                    prow += PS;
                    if (i < 15) {
                        va = *reinterpret_cast<const float4*>(prow);
                        vb = *reinterpret_cast<const float4*>(prow + 4);
                        vc = *reinterpret_cast<const float4*>(prow + 8);
                        vd = *reinterpret_cast<const float4*>(prow + 12);
                    }

                    #pragma unroll
                    for (int k = 0; k < KW; ++k) {
                        if (NPAIR == 2) {
                            unsigned long long w01, w23;
                            asm("ld.shared.v2.b64 {%0, %1}, [%2];"
                                : "=l"(w01), "=l"(w23)
                                : "r"(wadr + (uint32_t)(k * 128)));
                            #pragma unroll
                            for (int j = 0; j < 8; ++j) {
                                FMA2(acc2[0][j], w01, vp[j + k], acc2[0][j]);
                                FMA2(acc2[1][j], w23, vp[j + k], acc2[1][j]);
                            }
                        } else {
                            unsigned long long w01;
                            asm("ld.shared.b64 %0, [%1];"
                                : "=l"(w01)
                                : "r"(wadr + (uint32_t)(k * 128)));
                            #pragma unroll
                            for (int j = 0; j < 8; ++j)
                                FMA2(acc2[0][j], w01, vp[j + k], acc2[0][j]);
                        }
                    }
                    wadr += WROW * 4;
                }
            }

            // unpack packed accumulators -> accf[a = co offset][j]
            float accf[COW][8];
            #pragma unroll
            for (int pr = 0; pr < NPAIR; ++pr)
                #pragma unroll
                for (int j = 0; j < 8; ++j)
                    UNPACK2(accf[2 * pr][j], accf[2 * pr + 1][j], acc2[pr][j]);

            if (CI_SPLIT > 1) {      // butterfly: ALL ciq lanes get full sums
                #pragma unroll
                for (int a = 0; a < COW; ++a)
                    #pragma unroll
                    for (int j = 0; j < 8; ++j) {
                        float s = accf[a][j];
                        #pragma unroll
                        for (int off = CI_SPLIT >> 1; off > 0; off >>= 1)
                            s += __shfl_xor_sync(0xffffffffu, s, off);
                        accf[a][j] = s;
                    }
            }

            // epilogue spread across ciq lanes: each writes one float4
            float4 rO;
            if (doO) {
                const float* xr = &xsm[(colB + aa) * L + w0 + 4 * hh];
                const float4 x0 = *reinterpret_cast<const float4*>(xr);
                rO.x = x0.x + fmaxf(accf[aa][4 * hh + 0], 0.0f);
                rO.y = x0.y + fmaxf(accf[aa][4 * hh + 1], 0.0f);
                rO.z = x0.z + fmaxf(accf[aa][4 * hh + 2], 0.0f);
                rO.w = x0.w + fmaxf(accf[aa][4 * hh + 3], 0.0f);
                *reinterpret_cast<float4*>(
                    outB + (size_t)(co0 + colB + aa) * CHS + rowOff + w0 + 4 * hh)
                    = rO;
            }

            // compute transposed VALUES now, while xsm is stable (pre-arrive);
            // only the global stores are deferred under the barrier
            float rT[4];
            if (doT) {
                #pragma unroll
                for (int m = 0; m < 4; ++m) {
                    const int mm = 4 * tl + m;
                    const int a = mm >> 3, j = mm & 7;
                    if (w0 + j < L)
                        rT[m] = xsm[(colB + a) * L + w0 + j] +
                                fmaxf(accf[a][j], 0.0f);
                }
            }

            // prefetch next step's skip-connection row BEFORE the barrier
            float4 xn[NX];
            if (step + 1 < S) {
                #pragma unroll
                for (int it = 0; it < NX; ++it) {
                    int idx = tid + it * BLOCK;
                    if (idx < 32 * L4) {
                        int c = idx / L4, j = idx - c * L4;
                        xn[it] = *reinterpret_cast<const float4*>(
                            inB + (size_t)(co0 + c) * CHS + (size_t)pn * L + 4 * j);
                    }
                }
            }

            CLUSTER_ARRIVE();     // release our output row to peers
            __syncthreads();      // all local pp/xsm reads done before overwrite

            // -- local work hidden under the cluster barrier latency --
            // own 32 channels: store straight from registers (no L2 trip)
            if (doO)
                *reinterpret_cast<float4*>(
                    &pp[PP_OFF(co0 + colB + aa) + 4 + w0 + 4 * hh]) = rO;
            // transposed-copy stores (values already in registers)
            if (doT) {
                #pragma unroll
                for (int m = 0; m < 4; ++m) {
                    const int mm = 4 * tl + m;
                    const int a = mm >> 3, j = mm & 7;
                    if (w0 + j < L)
                        toutB[(size_t)(co0 + colB + a) * CHS +
                              (size_t)(w0 + j) * S + p] = rT[m];
                }
            }
            // commit the prefetched skip-connection row
            if (step + 1 < S) {
                #pragma unroll
                for (int it = 0; it < NX; ++it) {
                    int idx = tid + it * BLOCK;
                    if (idx < 32 * L4) {
                        int c = idx / L4, j = idx - c * L4;
                        *reinterpret_cast<float4*>(&xsm[c * L + 4 * j]) = xn[it];
                    }
                }
            }

            CLUSTER_WAIT();       // peers' slices now visible

            // peers' 96 channels: reload just-written out row p via L2
            for (int idx = tid; idx < 96 * L4; idx += BLOCK) {
                int ch = idx / L4, j = idx - ch * L4;
                int c  = (co0 + 32 + ch) & (C_ - 1);
                const float4 v = __ldcg(reinterpret_cast<const float4*>(
                    outB + (size_t)c * CHS + rowOff + 4 * j));
                *reinterpret_cast<float4*>(&pp[PP_OFF(c) + 4 + 4 * j]) = v;
            }
            __syncthreads();
        }
    }
    #undef PP_OFF
    #undef W_OFF
}

extern "C" void kernel_launch(void* const* d_in, const int* in_sizes, int n_in,
                              void* d_out, int out_size)
{
    const float* x    = (const float*)d_in[0];
    const float* w_ud = (const float*)d_in[1];
    const float* w_du = (const float*)d_in[2];
    const float* w_lr = (const float*)d_in[3];
    const float* w_rl = (const float*)d_in[4];
    float* out = (float*)d_out;

    float *b0, *b1, *b2;
    cudaGetSymbolAddress((void**)&b0, g_buf0);
    cudaGetSymbolAddress((void**)&b1, g_buf1);
    cudaGetSymbolAddress((void**)&b2, g_buf2);

    constexpr int WROW = KW * 32;
    constexpr int WBLK = 16 * WROW + 32;
    constexpr int WFL  = 8 * WBLK + 32;
    constexpr int SM_V = (WFL + 8 * (16 * (W_ + 16) + 32) + 32 + 32 * W_) * 4;
    constexpr int SM_H = (WFL + 8 * (16 * (H_ + 16) + 32) + 32 + 32 * H_) * 4;

    // vertical:  co2 x w8: 13 wt x 16 cot x 4 ciq = 832 thr (26 warps)
    // horizontal: co2 x w8: 5 wt x 16 cot x 8 ciq = 640 thr (20 warps)
    cudaFuncSetAttribute(scnn_pass<H_, W_, 4, 832, 2, false>,
                         cudaFuncAttributeMaxDynamicSharedMemorySize, SM_V);
    cudaFuncSetAttribute(scnn_pass<H_, W_, 4, 832, 2, true>,
                         cudaFuncAttributeMaxDynamicSharedMemorySize, SM_V);
    cudaFuncSetAttribute(scnn_pass<W_, H_, 8, 640, 2, false>,
                         cudaFuncAttributeMaxDynamicSharedMemorySize, SM_H);
    cudaFuncSetAttribute(scnn_pass<W_, H_, 8, 640, 2, true>,
                         cudaFuncAttributeMaxDynamicSharedMemorySize, SM_H);

    const dim3 grid(4, B_, 1);

    // pass 1: down  (scan H, conv along W), layout [B,C,H,W]
    scnn_pass<H_, W_, 4, 832, 2, false><<<grid, 832, SM_V>>>(
        x,  w_ud, b0, 0, nullptr);
    // pass 2: up — also emits [B,C,W,H]-transposed copy into b2
    scnn_pass<H_, W_, 4, 832, 2, true><<<grid, 832, SM_V>>>(
        b0, w_du, b1, 1, b2);
    // pass 3: left->right (scan W, conv along H), layout [B,C,W,H]
    scnn_pass<W_, H_, 8, 640, 2, false><<<grid, 640, SM_H>>>(
        b2, w_lr, b0, 0, nullptr);
    // pass 4: right->left — transposed copy goes straight to d_out ([B,C,H,W])
    scnn_pass<W_, H_, 8, 640, 2, true><<<grid, 640, SM_H>>>(
        b0, w_rl, b1, 1, out);
}